// round 1
// baseline (speedup 1.0000x reference)
#include <cuda_runtime.h>

namespace {

constexpr int Wd = 512;
constexpr int Hd = 512;
constexpr int KS = 15;
constexpr int PADR = 7;
constexpr int TILE_H = 32;
constexpr int HROWS = TILE_H + KS - 1;   // 46
constexpr int NT = 256;
constexpr int SMEM_BYTES = HROWS * Wd * (int)sizeof(float);  // 94208

__global__ void __launch_bounds__(NT, 2)
gauss_blur_kernel(const float* __restrict__ x, const float* __restrict__ sigma,
                  float* __restrict__ out, int C)
{
    extern __shared__ float hbuf[];   // [HROWS][Wd]

    const int strip = blockIdx.x;
    const int ch    = blockIdx.y;
    const int b     = blockIdx.z;
    const int tid   = threadIdx.x;
    const int r0    = strip * TILE_H;

    // ---- per-batch 1D Gaussian weights (separable; normalization eps negligible) ----
    const float sg  = sigma[b];
    const float inv = 1.0f / (2.0f * sg * sg + 1e-8f);
    float w[KS];
    float s = 0.0f;
#pragma unroll
    for (int i = 0; i < KS; ++i) {
        const float a = (float)(i - PADR);
        w[i] = expf(-a * a * inv);
        s += w[i];
    }
    const float rs = 1.0f / s;
#pragma unroll
    for (int i = 0; i < KS; ++i) w[i] *= rs;

    const float* __restrict__ xp = x   + (size_t)(b * C + ch) * (Hd * Wd);
    float* __restrict__       op = out + (size_t)(b * C + ch) * (Hd * Wd);

    const int sub = tid >> 7;         // 0..1
    const int c0  = (tid & 127) * 4;  // this thread's 4-col chunk

    // ================= Horizontal pass: global -> smem =================
    // rows rr = 0..HROWS-1 correspond to global rows r0-7+rr
#pragma unroll 1
    for (int it = 0; it < HROWS / 2; ++it) {
        const int rr = it * 2 + sub;
        const int gr = r0 - PADR + rr;
        float acc0 = 0.f, acc1 = 0.f, acc2 = 0.f, acc3 = 0.f;
        if ((unsigned)gr < (unsigned)Hd) {
            const float* rowp = xp + (size_t)gr * Wd;
#pragma unroll
            for (int k = 0; k < 5; ++k) {
                const int cb = c0 - 8 + 4 * k;
                float4 v = make_float4(0.f, 0.f, 0.f, 0.f);
                if (cb >= 0 && cb < Wd)
                    v = __ldg(reinterpret_cast<const float4*>(rowp + cb));
                const float vv[4] = {v.x, v.y, v.z, v.w};
#pragma unroll
                for (int q = 0; q < 4; ++q) {
                    // tap column cx = c0 - 8 + 4k + q; output col c0 + o
                    // weight index j = cx - (c0+o) + 7 = 4k + q - o - 1
#pragma unroll
                    for (int o = 0; o < 4; ++o) {
                        const int j = 4 * k + q - o - 1;
                        if (j >= 0 && j < KS) {
                            const float wj = w[j];
                            if (o == 0) acc0 = fmaf(vv[q], wj, acc0);
                            if (o == 1) acc1 = fmaf(vv[q], wj, acc1);
                            if (o == 2) acc2 = fmaf(vv[q], wj, acc2);
                            if (o == 3) acc3 = fmaf(vv[q], wj, acc3);
                        }
                    }
                }
            }
        }
        *reinterpret_cast<float4*>(&hbuf[rr * Wd + c0]) =
            make_float4(acc0, acc1, acc2, acc3);
    }
    __syncthreads();

    // ================= Vertical pass: smem -> global =================
    // output row (tile coords) t taps hbuf rows t..t+14
#pragma unroll 1
    for (int blk = 0; blk < 4; ++blk) {
        const int ob = sub * 16 + blk * 4;   // first of 4 output rows in tile coords
        float4 acc[4];
#pragma unroll
        for (int o = 0; o < 4; ++o) acc[o] = make_float4(0.f, 0.f, 0.f, 0.f);

#pragma unroll
        for (int rr = 0; rr < KS + 3; ++rr) {   // 18 smem rows: ob+0 .. ob+17
            const float4 v = *reinterpret_cast<const float4*>(&hbuf[(ob + rr) * Wd + c0]);
#pragma unroll
            for (int o = 0; o < 4; ++o) {
                const int j = rr - o;
                if (j >= 0 && j < KS) {
                    const float wj = w[j];
                    acc[o].x = fmaf(v.x, wj, acc[o].x);
                    acc[o].y = fmaf(v.y, wj, acc[o].y);
                    acc[o].z = fmaf(v.z, wj, acc[o].z);
                    acc[o].w = fmaf(v.w, wj, acc[o].w);
                }
            }
        }
#pragma unroll
        for (int o = 0; o < 4; ++o)
            *reinterpret_cast<float4*>(op + (size_t)(r0 + ob + o) * Wd + c0) = acc[o];
    }
}

}  // namespace

extern "C" void kernel_launch(void* const* d_in, const int* in_sizes, int n_in,
                              void* d_out, int out_size) {
    const float* x     = (const float*)d_in[0];
    const float* sigma = (const float*)d_in[1];
    float* out         = (float*)d_out;

    const int B = in_sizes[1];                      // 32
    const int C = in_sizes[0] / (B * Hd * Wd);      // 3

    cudaFuncSetAttribute(gauss_blur_kernel,
                         cudaFuncAttributeMaxDynamicSharedMemorySize, SMEM_BYTES);

    dim3 grid(Hd / TILE_H, C, B);
    gauss_blur_kernel<<<grid, NT, SMEM_BYTES>>>(x, sigma, out, C);
}

// round 2
// speedup vs baseline: 1.4089x; 1.4089x over previous
#include <cuda_runtime.h>

namespace {

constexpr int Wd   = 512;
constexpr int Hd   = 512;
constexpr int KS   = 15;
constexpr int PADR = 7;
constexpr int TW   = 256;                 // tile width
constexpr int TH   = 32;                  // tile height (output rows)
constexpr int HROWS = TH + KS - 1;        // 46 rows after horizontal pass
constexpr int NT   = 256;

__device__ __forceinline__ unsigned long long pack2(float lo, float hi) {
    unsigned long long r;
    asm("mov.b64 %0, {%1, %2};" : "=l"(r) : "f"(lo), "f"(hi));
    return r;
}
__device__ __forceinline__ void fma2(unsigned long long& d,
                                     unsigned long long a,
                                     unsigned long long b) {
    asm("fma.rn.f32x2 %0, %1, %2, %0;" : "+l"(d) : "l"(a), "l"(b));
}
__host__ __device__ constexpr int widx(int j) { return j < 8 ? j : 14 - j; }

__global__ void __launch_bounds__(NT, 4)
gauss_blur_kernel(const float* __restrict__ x, const float* __restrict__ sigma,
                  float* __restrict__ out, int C)
{
    __shared__ float hbuf[HROWS * TW];    // 46*256*4 = 47104 B -> 4 CTAs/SM

    const int tileX = blockIdx.x & 1;     // 0..1 : column tile
    const int strip = blockIdx.x >> 1;    // 0..15: row strip
    const int ch    = blockIdx.y;
    const int b     = blockIdx.z;
    const int tid   = threadIdx.x;

    const int col0 = tileX * TW;
    const int r0   = strip * TH;

    // ---- per-batch symmetric 1D Gaussian weights (8 distinct taps) ----
    const float sg  = sigma[b];
    const float inv = 1.0f / (2.0f * sg * sg + 1e-8f);
    float w[8];
    float s = 0.0f;
#pragma unroll
    for (int i = 0; i < 8; ++i) {
        const float a = (float)(7 - i);
        w[i] = __expf(-a * a * inv);
        s += (i < 7) ? 2.0f * w[i] : w[i];
    }
    const float rs = 1.0f / s;
#pragma unroll
    for (int i = 0; i < 8; ++i) w[i] *= rs;

    const size_t img = (size_t)(b * C + ch) * (Hd * Wd);
    const float* __restrict__ xp = x + img;
    float* __restrict__       op = out + img;

    const int tc   = tid & 63;            // float4-column within tile
    const int lc0  = tc * 4;
    const int rsel = tid >> 6;            // 0..3

    // ================= Horizontal pass: global -> smem =================
    const int gc0 = col0 + lc0;
#pragma unroll 1
    for (int it = 0; it < 12; ++it) {
        const int rr = it * 4 + rsel;     // hbuf row 0..47 (skip >=46)
        if (rr < HROWS) {
            const int gr = r0 - PADR + rr;
            float a0 = 0.f, a1 = 0.f, a2 = 0.f, a3 = 0.f;
            if ((unsigned)gr < (unsigned)Hd) {
                const float* rowp = xp + (size_t)gr * Wd;
#pragma unroll
                for (int k = 0; k < 5; ++k) {
                    const int gc = gc0 - 8 + 4 * k;
                    float4 v = make_float4(0.f, 0.f, 0.f, 0.f);
                    if (gc >= 0 && gc < Wd)
                        v = __ldg(reinterpret_cast<const float4*>(rowp + gc));
                    const float vv[4] = {v.x, v.y, v.z, v.w};
#pragma unroll
                    for (int q = 0; q < 4; ++q) {
#pragma unroll
                        for (int o = 0; o < 4; ++o) {
                            const int j = 4 * k + q - o - 1;  // compile-time
                            if (j >= 0 && j < KS) {
                                const float wj = w[widx(j)];
                                if (o == 0) a0 = fmaf(vv[q], wj, a0);
                                if (o == 1) a1 = fmaf(vv[q], wj, a1);
                                if (o == 2) a2 = fmaf(vv[q], wj, a2);
                                if (o == 3) a3 = fmaf(vv[q], wj, a3);
                            }
                        }
                    }
                }
            }
            *reinterpret_cast<float4*>(&hbuf[rr * TW + lc0]) =
                make_float4(a0, a1, a2, a3);
        }
    }
    __syncthreads();

    // ================= Vertical pass: smem -> global (f32x2) =================
    unsigned long long wp[8];
#pragma unroll
    for (int i = 0; i < 8; ++i) wp[i] = pack2(w[i], w[i]);

    const int rsub = rsel;                // 0..3 -> 8 output rows each
#pragma unroll 1
    for (int blk = 0; blk < 2; ++blk) {
        const int orow0 = rsub * 8 + blk * 4;   // tile-local first output row
        unsigned long long acc[4][2];
#pragma unroll
        for (int o = 0; o < 4; ++o) { acc[o][0] = 0ull; acc[o][1] = 0ull; }

#pragma unroll
        for (int rr = 0; rr < KS + 3; ++rr) {   // 18 smem rows
            const ulonglong2 v = *reinterpret_cast<const ulonglong2*>(
                &hbuf[(orow0 + rr) * TW + lc0]);
#pragma unroll
            for (int o = 0; o < 4; ++o) {
                const int j = rr - o;           // compile-time
                if (j >= 0 && j < KS) {
                    const unsigned long long wj = wp[widx(j)];
                    fma2(acc[o][0], v.x, wj);
                    fma2(acc[o][1], v.y, wj);
                }
            }
        }
#pragma unroll
        for (int o = 0; o < 4; ++o) {
            *reinterpret_cast<ulonglong2*>(
                op + (size_t)(r0 + orow0 + o) * Wd + col0 + lc0) =
                make_ulonglong2(acc[o][0], acc[o][1]);
        }
    }
}

}  // namespace

extern "C" void kernel_launch(void* const* d_in, const int* in_sizes, int n_in,
                              void* d_out, int out_size) {
    const float* x     = (const float*)d_in[0];
    const float* sigma = (const float*)d_in[1];
    float* out         = (float*)d_out;

    const int B = in_sizes[1];                      // 32
    const int C = in_sizes[0] / (B * Hd * Wd);      // 3

    dim3 grid((Wd / TW) * (Hd / TH), C, B);         // 32 x 3 x 32 = 3072
    gauss_blur_kernel<<<grid, NT>>>(x, sigma, out, C);
}

// round 3
// speedup vs baseline: 1.9852x; 1.4090x over previous
#include <cuda_runtime.h>

namespace {

constexpr int Wd = 512;
constexpr int Hd = 512;
constexpr int TH = 16;            // output rows per CTA
constexpr int NT = 256;

__device__ __forceinline__ unsigned long long pack2(float lo, float hi) {
    unsigned long long r;
    asm("mov.b64 %0, {%1, %2};" : "=l"(r) : "f"(lo), "f"(hi));
    return r;
}
__device__ __forceinline__ void fma2(unsigned long long& d,
                                     unsigned long long a,
                                     unsigned long long b) {
    asm("fma.rn.f32x2 %0, %1, %2, %0;" : "+l"(d) : "l"(a), "l"(b));
}
__host__ __device__ constexpr int widx(int j) { return j < 8 ? j : 14 - j; }

// horizontal packed-pair step: pair P=(x_s, x_{s+1}) feeds acc pairs
// ap0=(a0,a1) when j0=s-1 in [0,14], ap1=(a2,a3) when j1=s-3 in [0,14]
#define HPAIR(S, LO, HI)                                              \
    do {                                                              \
        if ((S) >= 1 && (S) <= 17) {                                  \
            unsigned long long P_ = pack2((LO), (HI));                \
            if ((S) >= 1 && (S) <= 15) fma2(ap0, P_, wp[widx((S)-1)]);\
            if ((S) >= 3 && (S) <= 17) fma2(ap1, P_, wp[widx((S)-3)]);\
        }                                                             \
    } while (0)

__global__ void __launch_bounds__(NT, 4)
gauss_kernel(const float* __restrict__ x, const float* __restrict__ sigma,
             float* __restrict__ out, int C)
{
    __shared__ float vbuf[TH * Wd];   // 32 KB: vertically-blurred strip

    const int strip = blockIdx.x;
    const int ch    = blockIdx.y;
    const int b     = blockIdx.z;
    const int tid   = threadIdx.x;
    const int r0    = strip * TH;

    // ---- symmetric 1D Gaussian weights (8 distinct), packed broadcast ----
    const float sg  = sigma[b];
    const float inv = 1.0f / (2.0f * sg * sg + 1e-8f);
    float w[8];
    float s = 0.0f;
#pragma unroll
    for (int i = 0; i < 8; ++i) {
        const float a = (float)(7 - i);
        w[i] = __expf(-a * a * inv);
        s += (i < 7) ? 2.0f * w[i] : w[i];
    }
    const float rs = 1.0f / s;
    unsigned long long wp[8];
#pragma unroll
    for (int i = 0; i < 8; ++i) { w[i] *= rs; wp[i] = pack2(w[i], w[i]); }

    const size_t img = (size_t)(b * C + ch) * (Hd * Wd);
    const float* __restrict__ xp = x + img;
    float* __restrict__       op = out + img;

    // ================= Stage 1: vertical, global -> vbuf =================
    // thread: 4 cols x 8 consecutive output rows; 22-row input window
    {
        const int g     = tid >> 7;          // 0..1 : row group
        const int cc    = tid & 127;         // col chunk (4 floats)
        const int gcol  = cc * 4;
        const int rbase = r0 + g * 8 - 7;    // first input row
        const float* colp = xp + gcol;

        unsigned long long acc[8][2];
#pragma unroll
        for (int o = 0; o < 8; ++o) { acc[o][0] = 0ull; acc[o][1] = 0ull; }

        const bool interior = (rbase >= 0) && (rbase + 21 < Hd);
        if (interior) {
#pragma unroll
            for (int rr = 0; rr < 22; ++rr) {
                const ulonglong2 v = *reinterpret_cast<const ulonglong2*>(
                    colp + (size_t)(rbase + rr) * Wd);
#pragma unroll
                for (int o = 0; o < 8; ++o) {
                    const int j = rr - o;
                    if (j >= 0 && j < 15) {
                        fma2(acc[o][0], v.x, wp[widx(j)]);
                        fma2(acc[o][1], v.y, wp[widx(j)]);
                    }
                }
            }
        } else {
#pragma unroll
            for (int rr = 0; rr < 22; ++rr) {
                const int gr = rbase + rr;
                if ((unsigned)gr < (unsigned)Hd) {
                    const ulonglong2 v = *reinterpret_cast<const ulonglong2*>(
                        colp + (size_t)gr * Wd);
#pragma unroll
                    for (int o = 0; o < 8; ++o) {
                        const int j = rr - o;
                        if (j >= 0 && j < 15) {
                            fma2(acc[o][0], v.x, wp[widx(j)]);
                            fma2(acc[o][1], v.y, wp[widx(j)]);
                        }
                    }
                }
            }
        }
#pragma unroll
        for (int o = 0; o < 8; ++o)
            *reinterpret_cast<ulonglong2*>(&vbuf[(g * 8 + o) * Wd + gcol]) =
                make_ulonglong2(acc[o][0], acc[o][1]);
    }
    __syncthreads();

    // ================= Stage 2: horizontal, vbuf -> global =================
    // thread: fixed col chunk, 8 rows (stride 2); f32x2 packed-pair taps
    {
        const int chunk = tid & 127;
        const int gc0   = chunk * 4;
        const int rsel  = tid >> 7;

        bool kv[5];
#pragma unroll
        for (int k = 0; k < 5; ++k) {
            const int gc = gc0 - 8 + 4 * k;
            kv[k] = (gc >= 0) && (gc < Wd);
        }

#pragma unroll 1
        for (int t = 0; t < 8; ++t) {
            const int row = rsel + 2 * t;
            const float* rp = &vbuf[row * Wd];

            unsigned long long ap0 = 0ull, ap1 = 0ull;
            float carry = 0.0f;
#pragma unroll
            for (int k = 0; k < 5; ++k) {
                float4 v = make_float4(0.f, 0.f, 0.f, 0.f);
                if (kv[k])
                    v = *reinterpret_cast<const float4*>(rp + (gc0 - 8 + 4 * k));
                if (k > 0) HPAIR(4 * k - 1, carry, v.x);
                HPAIR(4 * k + 0, v.x, v.y);
                HPAIR(4 * k + 1, v.y, v.z);
                HPAIR(4 * k + 2, v.z, v.w);
                carry = v.w;
            }
            *reinterpret_cast<ulonglong2*>(op + (size_t)(r0 + row) * Wd + gc0) =
                make_ulonglong2(ap0, ap1);
        }
    }
}

}  // namespace

extern "C" void kernel_launch(void* const* d_in, const int* in_sizes, int n_in,
                              void* d_out, int out_size) {
    const float* x     = (const float*)d_in[0];
    const float* sigma = (const float*)d_in[1];
    float* out         = (float*)d_out;

    const int B = in_sizes[1];                      // 32
    const int C = in_sizes[0] / (B * Hd * Wd);      // 3

    dim3 grid(Hd / TH, C, B);                       // 32 x 3 x 32 = 3072
    gauss_kernel<<<grid, NT>>>(x, sigma, out, C);
}

// round 4
// speedup vs baseline: 2.0283x; 1.0217x over previous
#include <cuda_runtime.h>

namespace {

constexpr int Wd = 512;
constexpr int Hd = 512;
constexpr int TH = 16;            // output rows per CTA
constexpr int VW = 528;           // padded vbuf width (8 zero cols each side)
constexpr int NT = 256;

__device__ __forceinline__ unsigned long long pack2(float lo, float hi) {
    unsigned long long r;
    asm("mov.b64 %0, {%1, %2};" : "=l"(r) : "f"(lo), "f"(hi));
    return r;
}
__device__ __forceinline__ void fma2(unsigned long long& d,
                                     unsigned long long a,
                                     unsigned long long b) {
    asm("fma.rn.f32x2 %0, %1, %2, %0;" : "+l"(d) : "l"(a), "l"(b));
}
__host__ __device__ constexpr int widx(int j) { return j < 8 ? j : 14 - j; }

__global__ void __launch_bounds__(NT, 4)
gauss_kernel(const float* __restrict__ x, const float* __restrict__ sigma,
             float* __restrict__ out, int C)
{
    __shared__ float vbuf[TH * VW];   // 33792 B -> 4 CTAs/SM

    const int strip = blockIdx.x;
    const int ch    = blockIdx.y;
    const int b     = blockIdx.z;
    const int tid   = threadIdx.x;
    const int r0    = strip * TH;

    // ---- symmetric 1D Gaussian weights (8 distinct), packed broadcast ----
    const float sg  = sigma[b];
    const float inv = 1.0f / (2.0f * sg * sg + 1e-8f);
    float w[8];
    float s = 0.0f;
#pragma unroll
    for (int i = 0; i < 8; ++i) {
        const float a = (float)(7 - i);
        w[i] = __expf(-a * a * inv);
        s += (i < 7) ? 2.0f * w[i] : w[i];
    }
    const float rs = 1.0f / s;
    unsigned long long wp[8];
#pragma unroll
    for (int i = 0; i < 8; ++i) { w[i] *= rs; wp[i] = pack2(w[i], w[i]); }

    const size_t img = (size_t)(b * C + ch) * (Hd * Wd);
    const float* __restrict__ xp = x + img;
    float* __restrict__       op = out + img;

    // ---- zero-fill column halos (cols 0..7 and 520..527, 16 rows) ----
    if (tid < 64) {
        const int row = tid >> 2;
        const int q   = tid & 3;
        const int cc  = (q < 2) ? q * 4 : 520 + (q - 2) * 4;
        *reinterpret_cast<float4*>(&vbuf[row * VW + cc]) =
            make_float4(0.f, 0.f, 0.f, 0.f);
    }

    // ================= Stage 1: vertical, global -> vbuf =================
    // thread: 2 cols x 16 rows; 30-row sliding input window
    {
        const int c0 = tid * 2;
        const float* colp = xp + c0;
        const int rbase = r0 - 7;

        unsigned long long acc[16];
#pragma unroll
        for (int o = 0; o < 16; ++o) acc[o] = 0ull;

        if (rbase >= 0 && rbase + 29 < Hd) {
            const float* p = colp + (size_t)rbase * Wd;
#pragma unroll
            for (int rr = 0; rr < 30; ++rr) {
                const unsigned long long v =
                    *reinterpret_cast<const unsigned long long*>(p);
                p += Wd;
#pragma unroll
                for (int o = 0; o < 16; ++o) {
                    const int j = rr - o;
                    if (j >= 0 && j < 15) fma2(acc[o], v, wp[widx(j)]);
                }
            }
        } else {
#pragma unroll
            for (int rr = 0; rr < 30; ++rr) {
                const int gr = rbase + rr;
                if ((unsigned)gr < (unsigned)Hd) {
                    const unsigned long long v =
                        *reinterpret_cast<const unsigned long long*>(
                            colp + (size_t)gr * Wd);
#pragma unroll
                    for (int o = 0; o < 16; ++o) {
                        const int j = rr - o;
                        if (j >= 0 && j < 15) fma2(acc[o], v, wp[widx(j)]);
                    }
                }
            }
        }
#pragma unroll
        for (int o = 0; o < 16; ++o)
            *reinterpret_cast<unsigned long long*>(&vbuf[o * VW + 8 + c0]) =
                acc[o];
    }
    __syncthreads();

    // ================= Stage 2: horizontal, vbuf -> global =================
    // thread: 4-col chunk x 8 rows; padded smem -> no column predicates
    {
        const int chunk = tid & 127;
        const int rsel  = tid >> 7;
        const int gc0   = chunk * 4;
        const float* basep = &vbuf[8 + gc0];

#pragma unroll
        for (int t = 0; t < 8; ++t) {
            const int row = rsel + 2 * t;
            const float* rp = basep + row * VW;

            float f[20];
            const float4 v0 = *reinterpret_cast<const float4*>(rp - 8);
            const float4 v1 = *reinterpret_cast<const float4*>(rp - 4);
            const float4 v2 = *reinterpret_cast<const float4*>(rp);
            const float4 v3 = *reinterpret_cast<const float4*>(rp + 4);
            const float4 v4 = *reinterpret_cast<const float4*>(rp + 8);
            f[0]=v0.x; f[1]=v0.y; f[2]=v0.z; f[3]=v0.w;
            f[4]=v1.x; f[5]=v1.y; f[6]=v1.z; f[7]=v1.w;
            f[8]=v2.x; f[9]=v2.y; f[10]=v2.z; f[11]=v2.w;
            f[12]=v3.x; f[13]=v3.y; f[14]=v3.z; f[15]=v3.w;
            f[16]=v4.x; f[17]=v4.y; f[18]=v4.z; f[19]=v4.w;

            // outputs (gc0+0..gc0+3); tap j for (o, input idx s): j = s-o-1
            unsigned long long ap0 = 0ull, ap1 = 0ull;
#pragma unroll
            for (int sidx = 1; sidx <= 17; ++sidx) {
                const unsigned long long P = pack2(f[sidx], f[sidx + 1]);
                if (sidx >= 1 && sidx <= 15) fma2(ap0, P, wp[widx(sidx - 1)]);
                if (sidx >= 3 && sidx <= 17) fma2(ap1, P, wp[widx(sidx - 3)]);
            }
            *reinterpret_cast<ulonglong2*>(op + (size_t)(r0 + row) * Wd + gc0) =
                make_ulonglong2(ap0, ap1);
        }
    }
}

}  // namespace

extern "C" void kernel_launch(void* const* d_in, const int* in_sizes, int n_in,
                              void* d_out, int out_size) {
    const float* x     = (const float*)d_in[0];
    const float* sigma = (const float*)d_in[1];
    float* out         = (float*)d_out;

    const int B = in_sizes[1];                      // 32
    const int C = in_sizes[0] / (B * Hd * Wd);      // 3

    dim3 grid(Hd / TH, C, B);                       // 32 x 3 x 32 = 3072
    gauss_kernel<<<grid, NT>>>(x, sigma, out, C);
}